// round 16
// baseline (speedup 1.0000x reference)
#include <cuda_runtime.h>
#include <cstdint>
#include <cmath>

// Fixed shapes
#define BB   4
#define NN   4096
#define CC   128
#define DPAD 132        // 3 pts + 128 feats + 1 zero pad (exact no-op in the chain)
#define NPT  1024
#define TILE 128
#define KT   33         // 132 = 4 * 33, ascending-k chunks
#define NBT  32         // NN / TILE
#define NTRI (NBT * (NBT + 1) / 2)   // 528 lower-triangle blocks

// Statics: k-major features, norms, full dist matrix (268 MB)
__device__ float g_G[BB][DPAD][NN];
__device__ float g_aa[BB][NN];
__device__ float g_dist[(size_t)BB * NN * NN];

// ---------------------------------------------------------------------------
// Prep: k-major G + aa in exact Grace/LLVM NEON reduce order (frozen).
// ---------------------------------------------------------------------------
__global__ void prep_kernel(const float* __restrict__ pts,
                            const float* __restrict__ feat)
{
    int t = blockIdx.x * blockDim.x + threadIdx.x;
    if (t >= BB * NN) return;
    int b = t / NN;
    int n = t % NN;

    float row[DPAD];
    row[0] = pts[((size_t)b * NN + n) * 3 + 0];
    row[1] = pts[((size_t)b * NN + n) * 3 + 1];
    row[2] = pts[((size_t)b * NN + n) * 3 + 2];

    const float* fb = feat + (size_t)b * CC * NN + n;
    #pragma unroll 4
    for (int c = 0; c < CC; c++) row[3 + c] = fb[(size_t)c * NN];
    row[131] = 0.0f;

    float v0[4] = {0.f, 0.f, 0.f, 0.f};
    float v1[4] = {0.f, 0.f, 0.f, 0.f};
    #pragma unroll
    for (int i = 0; i < 16; i++) {
        #pragma unroll
        for (int j = 0; j < 4; j++) {
            float x0 = row[8 * i + j];
            v0[j] = __fmaf_rn(x0, x0, v0[j]);
            float x1 = row[8 * i + 4 + j];
            v1[j] = __fmaf_rn(x1, x1, v1[j]);
        }
    }
    float l0 = __fadd_rn(v0[0], v1[0]);
    float l1 = __fadd_rn(v0[1], v1[1]);
    float l2 = __fadd_rn(v0[2], v1[2]);
    float l3 = __fadd_rn(v0[3], v1[3]);
    float h  = __fadd_rn(__fadd_rn(l0, l1), __fadd_rn(l2, l3));
    h = __fmaf_rn(row[128], row[128], h);
    h = __fmaf_rn(row[129], row[129], h);
    h = __fmaf_rn(row[130], row[130], h);
    g_aa[b][n] = h;

    #pragma unroll 4
    for (int k = 0; k < DPAD; k++) g_G[b][k][n] = row[k];
}

// ---------------------------------------------------------------------------
// GEMM (symmetric-half, 128x128 tiles, 8x8 microtile, 256 threads).
// Frozen numerics; mirror bit-exact; staged through retired As buffer.
// (Unchanged from round 15.)
// ---------------------------------------------------------------------------
__global__ void __launch_bounds__(256, 2) gemm_kernel()
{
    __shared__ __align__(16) float As[KT][TILE];
    __shared__ __align__(16) float Bs[KT][TILE];

    int l  = blockIdx.x;
    int bi = (int)((sqrtf(8.0f * (float)l + 1.0f) - 1.0f) * 0.5f);
    while ((bi + 1) * (bi + 2) / 2 <= l) bi++;
    while (bi * (bi + 1) / 2 > l)        bi--;
    int bj = l - bi * (bi + 1) / 2;

    const int b  = blockIdx.y;
    const int i0 = bi * TILE;
    const int j0 = bj * TILE;

    const int tx = threadIdx.x % 16;
    const int ty = threadIdx.x / 16;
    const int ri = ty * 8;
    const int rj = tx * 8;

    float acc[8][8];
    #pragma unroll
    for (int ii = 0; ii < 8; ii++)
        #pragma unroll
        for (int jj = 0; jj < 8; jj++)
            acc[ii][jj] = 0.0f;

    #pragma unroll 1
    for (int kb = 0; kb < DPAD; kb += KT) {
        __syncthreads();
        for (int idx = threadIdx.x; idx < KT * TILE; idx += 256) {
            int k = idx >> 7;
            int n = idx & 127;
            As[k][n] = g_G[b][kb + k][i0 + n];
            Bs[k][n] = g_G[b][kb + k][j0 + n];
        }
        __syncthreads();

        #pragma unroll 3
        for (int k = 0; k < KT; k++) {
            float4 a0 = *(const float4*)&As[k][ri];
            float4 a1 = *(const float4*)&As[k][ri + 4];
            float4 b0 = *(const float4*)&Bs[k][rj];
            float4 b1 = *(const float4*)&Bs[k][rj + 4];
            float av[8] = {a0.x, a0.y, a0.z, a0.w, a1.x, a1.y, a1.z, a1.w};
            float bv[8] = {b0.x, b0.y, b0.z, b0.w, b1.x, b1.y, b1.z, b1.w};
            #pragma unroll
            for (int ii = 0; ii < 8; ii++)
                #pragma unroll
                for (int jj = 0; jj < 8; jj++)
                    acc[ii][jj] = __fmaf_rn(av[ii], bv[jj], acc[ii][jj]);
        }
    }

    float aai[8], aaj[8];
    #pragma unroll
    for (int ii = 0; ii < 8; ii++) aai[ii] = g_aa[b][i0 + ri + ii];
    #pragma unroll
    for (int jj = 0; jj < 8; jj++) aaj[jj] = g_aa[b][j0 + rj + jj];

    float dv[8][8];
    #pragma unroll
    for (int ii = 0; ii < 8; ii++)
        #pragma unroll
        for (int jj = 0; jj < 8; jj++)
            dv[ii][jj] = __fadd_rn(__fadd_rn(aai[ii], aaj[jj]),
                                   -__fmul_rn(2.0f, acc[ii][jj]));

    float* db = g_dist + ((size_t)b << 24);

    #pragma unroll
    for (int ii = 0; ii < 8; ii++) {
        float4 o0 = make_float4(dv[ii][0], dv[ii][1], dv[ii][2], dv[ii][3]);
        float4 o1 = make_float4(dv[ii][4], dv[ii][5], dv[ii][6], dv[ii][7]);
        size_t base = (size_t)(i0 + ri + ii) * NN + (j0 + rj);
        *(float4*)&db[base]     = o0;
        *(float4*)&db[base + 4] = o1;
    }

    if (i0 != j0) {
        float (*Ts)[129] = (float (*)[129])&As[0][0];
        #pragma unroll 1
        for (int c = 0; c < 4; c++) {
            __syncthreads();
            if ((tx >> 2) == c) {
                int jb = rj - 32 * c;
                #pragma unroll
                for (int jj = 0; jj < 8; jj++)
                    #pragma unroll
                    for (int ii = 0; ii < 8; ii++)
                        Ts[jb + jj][ri + ii] = dv[ii][jj];
            }
            __syncthreads();
            int r  = threadIdx.x >> 3;
            int cc = (threadIdx.x & 7) * 16;
            size_t base = (size_t)(j0 + 32 * c + r) * NN + (i0 + cc);
            #pragma unroll
            for (int q = 0; q < 4; q++) {
                float4 o = make_float4(Ts[r][cc + 4*q], Ts[r][cc + 4*q + 1],
                                       Ts[r][cc + 4*q + 2], Ts[r][cc + 4*q + 3]);
                *(float4*)&db[base + 4*q] = o;
            }
        }
    }
}

// ---------------------------------------------------------------------------
// FPS v2: 1 CTA/batch, 256 threads x 16 pts (4 independent float4 -> MLP=4),
// 8 warps, ONE barrier per step (parity-double-buffered slots, every thread
// redundantly reduces the 8 warp candidates). Semantics frozen: per-element
// fminf, argmax with first-occurrence (smallest index) tie-break.
// ---------------------------------------------------------------------------
__global__ void __launch_bounds__(256) fps_kernel(float* __restrict__ out)
{
    const int b    = blockIdx.x;
    const int t    = threadIdx.x;
    const int lane = t & 31;
    const int w    = t >> 5;

    const float* db = g_dist + ((size_t)b << 24);
    float* outb = out + b * NPT;

    __shared__ float s_v[2][8];
    __shared__ int   s_i[2][8];

    float m[16];
    #pragma unroll
    for (int q = 0; q < 16; q++) m[q] = 1e10f;

    int cur = 0;

    for (int s = 0; s < NPT; s++) {
        const int p = s & 1;
        if (t == 0) outb[s] = (float)cur;

        const float* row = db + ((size_t)cur << 12);
        // 4 independent coalesced float4 loads: point q*1024 + 4t + j
        float4 d0 = *(const float4*)(row + 4 * t);
        float4 d1 = *(const float4*)(row + 1024 + 4 * t);
        float4 d2 = *(const float4*)(row + 2048 + 4 * t);
        float4 d3 = *(const float4*)(row + 3072 + 4 * t);

        m[0]  = fminf(m[0],  d0.x); m[1]  = fminf(m[1],  d0.y);
        m[2]  = fminf(m[2],  d0.z); m[3]  = fminf(m[3],  d0.w);
        m[4]  = fminf(m[4],  d1.x); m[5]  = fminf(m[5],  d1.y);
        m[6]  = fminf(m[6],  d1.z); m[7]  = fminf(m[7],  d1.w);
        m[8]  = fminf(m[8],  d2.x); m[9]  = fminf(m[9],  d2.y);
        m[10] = fminf(m[10], d2.z); m[11] = fminf(m[11], d2.w);
        m[12] = fminf(m[12], d3.x); m[13] = fminf(m[13], d3.y);
        m[14] = fminf(m[14], d3.z); m[15] = fminf(m[15], d3.w);

        // Local argmax, scanned in ascending global index (strict > => first occurrence).
        float v = m[0]; int idx = 4 * t;
        #pragma unroll
        for (int q = 0; q < 4; q++) {
            #pragma unroll
            for (int j = 0; j < 4; j++) {
                if (q == 0 && j == 0) continue;
                float mv = m[q * 4 + j];
                if (mv > v) { v = mv; idx = 1024 * q + 4 * t + j; }
            }
        }

        // Warp reduce (explicit index tie-break).
        #pragma unroll
        for (int off = 16; off; off >>= 1) {
            float v2 = __shfl_down_sync(0xffffffffu, v, off);
            int   i2 = __shfl_down_sync(0xffffffffu, idx, off);
            if (v2 > v || (v2 == v && i2 < idx)) { v = v2; idx = i2; }
        }
        if (lane == 0) { s_v[p][w] = v; s_i[p][w] = idx; }
        __syncthreads();

        // Every thread reduces the 8 slots (order-independent: explicit compares).
        float bv = s_v[p][0]; int bi = s_i[p][0];
        #pragma unroll
        for (int u = 1; u < 8; u++) {
            float rv = s_v[p][u]; int ri = s_i[p][u];
            if (rv > bv || (rv == bv && ri < bi)) { bv = rv; bi = ri; }
        }
        cur = bi;
    }
}

// ---------------------------------------------------------------------------
extern "C" void kernel_launch(void* const* d_in, const int* in_sizes, int n_in,
                              void* d_out, int out_size)
{
    const float* points   = nullptr;
    const float* features = nullptr;
    for (int i = 0; i < n_in; i++) {
        long long sz = in_sizes[i];
        if (sz == (long long)BB * NN * 3)       points   = (const float*)d_in[i];
        else if (sz == (long long)BB * CC * NN) features = (const float*)d_in[i];
    }
    if (!points)   points   = (const float*)d_in[0];
    if (!features) features = (const float*)d_in[1];

    float* out = (float*)d_out;
    (void)out_size;

    prep_kernel<<<(BB * NN + 255) / 256, 256>>>(points, features);

    dim3 grid(NTRI, BB);                  // 528 triangle blocks x 4 batches
    gemm_kernel<<<grid, 256>>>();

    fps_kernel<<<BB, 256>>>(out);
}